// round 1
// baseline (speedup 1.0000x reference)
#include <cuda_runtime.h>
#include <stdint.h>
#include <math.h>

#define NB    16384
#define NPRE  1024
#define NPOST 512
#define BATCH 2
#define NMS_THRESH 0.8f

// ---------------- device scratch (no allocations allowed) ----------------
__device__ unsigned long long g_keys[BATCH][NB];
__device__ unsigned int       g_hist[BATCH][65536];
__device__ int                g_cut[BATCH];
__device__ int                g_candCnt[BATCH];
__device__ unsigned long long g_cand[BATCH][8192];
__device__ int                g_topidx[BATCH][NPRE];
__device__ float              g_bev[BATCH][NPRE][16];
// layout per box: [0]x [1]y [2]dx [3]dy [4]cos [5]sin [6..9]cx [10..13]cy [14]area [15]radius
__device__ unsigned int       g_mask[BATCH][NPRE][32];
__device__ int                g_pos[BATCH][NPOST];

// ---------------- helpers ----------------
__device__ __forceinline__ unsigned fmap(float f) {
    unsigned u = __float_as_uint(f);
    return u ^ ((u & 0x80000000u) ? 0xFFFFFFFFu : 0x80000000u);
}

// ---------------- kernel 0: zero scratch ----------------
__global__ void k_zero() {
    int t = blockIdx.x * blockDim.x + threadIdx.x;
    if (t < BATCH * 65536) ((unsigned*)g_hist)[t] = 0u;
    if (t < BATCH) g_candCnt[t] = 0;
}

// ---------------- kernel 1: score keys + histogram ----------------
__global__ void k_keys(const float* __restrict__ cls) {
    int t = blockIdx.x * blockDim.x + threadIdx.x;
    if (t >= BATCH * NB) return;
    int b = t >> 14, i = t & (NB - 1);
    const float* c = cls + (size_t)(b * NB + i) * 3;
    float s = fmaxf(fmaxf(c[0], c[1]), c[2]);
    unsigned u = fmap(s);
    // key: high = mapped score (desc), low = ~index (ties -> smaller index first)
    unsigned long long key = ((unsigned long long)u << 32) | (unsigned)(~(unsigned)i);
    g_keys[b][i] = key;
    atomicAdd(&g_hist[b][u >> 16], 1u);
}

// ---------------- kernel 2: find histogram cutoff bin (top-1024) ----------------
__global__ void k_cut() {
    int b = blockIdx.x, t = threadIdx.x;  // blockDim = 1024
    __shared__ int sh[1024];
    int base = 65535 - t * 64;
    int p = 0;
    for (int k = 0; k < 64; k++) p += (int)g_hist[b][base - k];
    sh[t] = p;
    __syncthreads();
    for (int o = 1; o < 1024; o <<= 1) {
        int v = (t >= o) ? sh[t - o] : 0;
        __syncthreads();
        sh[t] += v;
        __syncthreads();
    }
    int incl = sh[t], excl = incl - p;
    if (excl < NPRE && incl >= NPRE) {
        int cum = excl;
        for (int k = 0; k < 64; k++) {
            cum += (int)g_hist[b][base - k];
            if (cum >= NPRE) { g_cut[b] = base - k; break; }
        }
    }
}

// ---------------- kernel 3: compact candidates ----------------
__global__ void k_compact() {
    int t = blockIdx.x * blockDim.x + threadIdx.x;
    if (t >= BATCH * NB) return;
    int b = t >> 14, i = t & (NB - 1);
    unsigned long long key = g_keys[b][i];
    int bin = (int)(unsigned)(key >> 48);
    if (bin >= g_cut[b]) {
        int p = atomicAdd(&g_candCnt[b], 1);
        if (p < 8192) g_cand[b][p] = key;
    }
}

// ---------------- kernel 4: sort candidates, emit top-1024 indices ----------------
__global__ void k_sorttop() {
    __shared__ unsigned long long arr[4096];   // 32 KB
    int b = blockIdx.x, t = threadIdx.x;       // blockDim = 1024
    int cnt = g_candCnt[b]; if (cnt > 4096) cnt = 4096;
    for (int i = t; i < 4096; i += 1024) arr[i] = (i < cnt) ? g_cand[b][i] : 0ULL;
    __syncthreads();
    for (int size = 2; size <= 4096; size <<= 1) {
        for (int stride = size >> 1; stride > 0; stride >>= 1) {
            for (int q = t; q < 2048; q += 1024) {
                int i = ((q & ~(stride - 1)) << 1) | (q & (stride - 1));
                int j = i + stride;
                bool desc = ((i & size) == 0);
                unsigned long long a = arr[i], c = arr[j];
                if (desc ? (a < c) : (a > c)) { arr[i] = c; arr[j] = a; }
            }
            __syncthreads();
        }
    }
    g_topidx[b][t] = (int)(~(unsigned)(arr[t] & 0xFFFFFFFFULL));
}

// ---------------- kernel 5: precompute BEV geometry for selected ----------------
__global__ void k_bev(const float* __restrict__ boxes) {
    int t = blockIdx.x * blockDim.x + threadIdx.x;
    if (t >= BATCH * NPRE) return;
    int b = t >> 10, k = t & (NPRE - 1);
    int sel = g_topidx[b][k];
    const float* p = boxes + (size_t)(b * NB + sel) * 7;
    float x = p[0], y = p[1], dx = p[3], dy = p[4], ry = p[6];
    float c = (float)cos((double)ry);
    float s = (float)sin((double)ry);
    float* o = g_bev[b][k];
    o[0] = x; o[1] = y; o[2] = dx; o[3] = dy; o[4] = c; o[5] = s;
    const float offx[4] = { 0.5f, -0.5f, -0.5f,  0.5f };
    const float offy[4] = { 0.5f,  0.5f, -0.5f, -0.5f };
#pragma unroll
    for (int q = 0; q < 4; q++) {
        float lx = dx * offx[q], ly = dy * offy[q];
        o[6 + q]  = x + lx * c - ly * s;
        o[10 + q] = y + lx * s + ly * c;
    }
    o[14] = dx * dy;
    o[15] = 0.5f * sqrtf(dx * dx + dy * dy);
}

// ---------------- faithful replica of reference pairwise IoU ----------------
__device__ float pair_iou(const float* __restrict__ A, const float* __restrict__ B) {
    float ax[4], ay[4], bx[4], by[4];
#pragma unroll
    for (int k = 0; k < 4; k++) { ax[k] = A[6 + k]; ay[k] = A[10 + k]; bx[k] = B[6 + k]; by[k] = B[10 + k]; }
    float dax[4], day[4], dbx[4], dby[4];
#pragma unroll
    for (int k = 0; k < 4; k++) {
        dax[k] = ax[(k + 1) & 3] - ax[k];  day[k] = ay[(k + 1) & 3] - ay[k];
        dbx[k] = bx[(k + 1) & 3] - bx[k];  dby[k] = by[(k + 1) & 3] - by[k];
    }
    float px[24], py[24]; int mk[24];
#pragma unroll
    for (int p = 0; p < 4; p++) {
#pragma unroll
        for (int q = 0; q < 4; q++) {
            int id = p * 4 + q;
            float den = dax[p] * dby[q] - day[p] * dbx[q];
            float ddx = bx[q] - ax[p], ddy = by[q] - ay[p];
            bool nz = fabsf(den) > 1e-8f;
            float dens = nz ? den : 1.0f;
            float tt = (ddx * dby[q] - ddy * dbx[q]) / dens;
            float uu = (ddx * day[p] - ddy * dax[p]) / dens;
            mk[id] = (nz && tt >= 0.f && tt <= 1.f && uu >= 0.f && uu <= 1.f) ? 1 : 0;
            px[id] = ax[p] + tt * dax[p];
            py[id] = ay[p] + tt * day[p];
        }
    }
    float Bx = B[0], By = B[1], Bdx = B[2], Bdy = B[3], Bc = B[4], Bs = B[5];
    float Ax = A[0], Ay = A[1], Adx = A[2], Ady = A[3], Ac = A[4], As = A[5];
#pragma unroll
    for (int k = 0; k < 4; k++) {
        px[16 + k] = ax[k]; py[16 + k] = ay[k];
        float rx = ax[k] - Bx, ry = ay[k] - By;
        float qx = rx * Bc + ry * Bs, qy = -rx * Bs + ry * Bc;
        mk[16 + k] = (fabsf(qx) <= Bdx * 0.5f + 1e-5f) && (fabsf(qy) <= Bdy * 0.5f + 1e-5f);
        px[20 + k] = bx[k]; py[20 + k] = by[k];
        float rx2 = bx[k] - Ax, ry2 = by[k] - Ay;
        float qx2 = rx2 * Ac + ry2 * As, qy2 = -rx2 * As + ry2 * Ac;
        mk[20 + k] = (fabsf(qx2) <= Adx * 0.5f + 1e-5f) && (fabsf(qy2) <= Ady * 0.5f + 1e-5f);
    }
    int cnt = 0; float sx = 0.f, sy = 0.f;
    for (int k = 0; k < 24; k++) if (mk[k]) { cnt++; sx += px[k]; sy += py[k]; }
    float inv = 1.0f / (float)(cnt > 0 ? cnt : 1);
    float cx = sx * inv, cy = sy * inv;
    float ang[24];
    for (int k = 0; k < 24; k++)
        ang[k] = mk[k] ? atan2f(py[k] - cy, px[k] - cx) : 1e9f;
    // stable insertion sort ascending by angle (matches stable jnp.argsort)
    for (int i = 1; i < 24; i++) {
        float a = ang[i], xx = px[i], yy = py[i]; int m = mk[i];
        int j = i - 1;
        while (j >= 0 && ang[j] > a) {
            ang[j + 1] = ang[j]; px[j + 1] = px[j]; py[j + 1] = py[j]; mk[j + 1] = mk[j];
            j--;
        }
        ang[j + 1] = a; px[j + 1] = xx; py[j + 1] = yy; mk[j + 1] = m;
    }
    float fx = px[0], fy = py[0];
    float qx[24], qy[24];
    for (int k = 0; k < 24; k++) { qx[k] = mk[k] ? px[k] : fx; qy[k] = mk[k] ? py[k] : fy; }
    float cr = 0.f;
    for (int k = 0; k < 24; k++) {
        int kn = (k + 1) % 24;
        cr += qx[k] * qy[kn] - qy[k] * qx[kn];
    }
    float inter = 0.5f * fabsf(cr);
    return inter / fmaxf(A[14] + B[14] - inter, 1e-6f);
}

// ---------------- kernel 6: suppression bitmask ----------------
__global__ void k_mask() {
    int b = blockIdx.y;
    int g = blockIdx.x * blockDim.x + threadIdx.x;   // 0 .. 32767
    int i = g >> 5, w = g & 31;
    __shared__ float sx[NPRE], sy[NPRE], sa[NPRE], sr[NPRE];
    for (int k = threadIdx.x; k < NPRE; k += blockDim.x) {
        const float* bp = g_bev[b][k];
        sx[k] = bp[0]; sy[k] = bp[1]; sa[k] = bp[14]; sr[k] = bp[15];
    }
    __syncthreads();
    const float* Ai = g_bev[b][i];
    float xi = Ai[0], yi = Ai[1], ai = Ai[14], ri = Ai[15];
    unsigned word = 0u;
    for (int jj = 0; jj < 32; jj++) {
        int j = w * 32 + jj;
        if (j <= i) continue;
        float ddx = xi - sx[j], ddy = yi - sy[j];
        float rs = ri + sr[j] + 1e-3f;
        if (ddx * ddx + ddy * ddy >= rs * rs) continue;          // disjoint -> IoU 0
        float aj = sa[j];
        float amin = fminf(ai, aj), amax = fmaxf(ai, aj);
        if (amin <= 0.79f * amax) continue;                       // IoU <= amin/amax < 0.8
        float iou = pair_iou(Ai, g_bev[b][j]);
        if (iou > NMS_THRESH) word |= (1u << jj);
    }
    g_mask[b][i][w] = word;
}

// ---------------- kernel 7: greedy NMS (one warp per batch) + compaction ----------------
__global__ void k_nms() {
    int b = blockIdx.x;
    int lane = threadIdx.x;                // blockDim = 32
    unsigned supp = 0u;
    const unsigned* M = &g_mask[b][0][0];
    for (int i = 0; i < NPRE; i++) {
        unsigned ow = __shfl_sync(0xffffffffu, supp, i >> 5);
        if (!((ow >> (i & 31)) & 1u)) supp |= M[i * 32 + lane];
    }
    unsigned keep = ~supp;
    int c = __popc(keep);
    int incl = c;
    for (int o = 1; o < 32; o <<= 1) {
        int v = __shfl_up_sync(0xffffffffu, incl, o);
        if (lane >= o) incl += v;
    }
    int excl = incl - c;
    for (int s = lane; s < NPOST; s += 32) g_pos[b][s] = -1;
    __syncwarp();
    unsigned m = keep;
    int slot = excl;
    while (m) {
        if (slot >= NPOST) break;
        int bit = __ffs(m) - 1;
        g_pos[b][slot++] = lane * 32 + bit;
        m &= (m - 1);
    }
}

// ---------------- kernel 8: write outputs ----------------
// layout (float32): rois[2][512][7] | scores[2][512] | labels[2][512] | logits[2][512][3]
__global__ void k_out(const float* __restrict__ boxes, const float* __restrict__ cls,
                      float* __restrict__ out) {
    int t = blockIdx.x * blockDim.x + threadIdx.x;
    if (t >= BATCH * NPOST) return;
    int b = t >> 9, k = t & (NPOST - 1);
    int p = g_pos[b][k];
    float r0 = 0.f, r1 = 0.f, r2 = 0.f, r3 = 0.f, r4 = 0.f, r5 = 0.f, r6 = 0.f;
    float l0 = 0.f, l1 = 0.f, l2 = 0.f, score = 0.f, lab = 1.f;
    if (p >= 0) {
        int sel = g_topidx[b][p];
        const float* bp = boxes + (size_t)(b * NB + sel) * 7;
        r0 = bp[0]; r1 = bp[1]; r2 = bp[2]; r3 = bp[3]; r4 = bp[4]; r5 = bp[5]; r6 = bp[6];
        const float* cp = cls + (size_t)(b * NB + sel) * 3;
        l0 = cp[0]; l1 = cp[1]; l2 = cp[2];
        int a = 0; float best = l0;
        if (l1 > best) { best = l1; a = 1; }
        if (l2 > best) { best = l2; a = 2; }
        score = best; lab = (float)(a + 1);
    }
    int s = b * NPOST + k;
    float* ro = out + (size_t)s * 7;
    ro[0] = r0; ro[1] = r1; ro[2] = r2; ro[3] = r3; ro[4] = r4; ro[5] = r5; ro[6] = r6;
    out[BATCH * NPOST * 7 + s] = score;
    out[BATCH * NPOST * 8 + s] = lab;
    float* lo = out + BATCH * NPOST * 9 + (size_t)s * 3;
    lo[0] = l0; lo[1] = l1; lo[2] = l2;
}

// ---------------- launch ----------------
extern "C" void kernel_launch(void* const* d_in, const int* in_sizes, int n_in,
                              void* d_out, int out_size) {
    const float* boxes = (const float*)d_in[0];
    const float* cls   = (const float*)d_in[1];
    // defensive: identify inputs by size (boxes = 2*16384*7, cls = 2*16384*3)
    if (n_in >= 2 && in_sizes[0] == BATCH * NB * 3) {
        const float* tmp = boxes; boxes = cls; cls = tmp;
    }
    float* out = (float*)d_out;
    (void)out_size;

    k_zero   <<<(BATCH * 65536 + 255) / 256, 256>>>();
    k_keys   <<<(BATCH * NB + 255) / 256, 256>>>(cls);
    k_cut    <<<BATCH, 1024>>>();
    k_compact<<<(BATCH * NB + 255) / 256, 256>>>();
    k_sorttop<<<BATCH, 1024>>>();
    k_bev    <<<(BATCH * NPRE + 255) / 256, 256>>>(boxes);
    k_mask   <<<dim3(128, BATCH), 256>>>();
    k_nms    <<<BATCH, 32>>>();
    k_out    <<<(BATCH * NPOST + 255) / 256, 256>>>(boxes, cls, out);
}

// round 2
// speedup vs baseline: 2.3860x; 2.3860x over previous
#include <cuda_runtime.h>
#include <stdint.h>
#include <math.h>

#define NB    16384
#define NPRE  1024
#define NPOST 512
#define BATCH 2
#define NMS_THRESH 0.8f
#define PAIR_CAP 32768

// ---------------- device scratch (no allocations allowed) ----------------
__device__ unsigned long long g_keys[BATCH][NB];
__device__ unsigned int       g_hist[BATCH][65536];
__device__ int                g_cut[BATCH];
__device__ int                g_candCnt[BATCH];
__device__ unsigned long long g_cand[BATCH][8192];
__device__ int                g_topidx[BATCH][NPRE];
__device__ float              g_bev[BATCH][NPRE][16];
// per box: [0]x [1]y [2]dx [3]dy [4]cos [5]sin [6..9]cx [10..13]cy [14]area [15]radius
__device__ unsigned int       g_mask[BATCH][NPRE][32];
__device__ int                g_pairCnt[BATCH];
__device__ unsigned int       g_pairs[BATCH][PAIR_CAP];
__device__ int                g_pos[BATCH][NPOST];

// ---------------- helpers ----------------
__device__ __forceinline__ unsigned fmap(float f) {
    unsigned u = __float_as_uint(f);
    return u ^ ((u & 0x80000000u) ? 0xFFFFFFFFu : 0x80000000u);
}

// ---------------- kernel 0: zero scratch ----------------
__global__ void k_zero() {
    int t = blockIdx.x * blockDim.x + threadIdx.x;
    if (t < BATCH * 65536) ((unsigned*)g_hist)[t] = 0u;
    if (t < BATCH * NPRE * 32) ((unsigned*)g_mask)[t] = 0u;
    if (t < BATCH) { g_candCnt[t] = 0; g_pairCnt[t] = 0; }
}

// ---------------- kernel 1: score keys + histogram ----------------
__global__ void k_keys(const float* __restrict__ cls) {
    int t = blockIdx.x * blockDim.x + threadIdx.x;
    if (t >= BATCH * NB) return;
    int b = t >> 14, i = t & (NB - 1);
    const float* c = cls + (size_t)(b * NB + i) * 3;
    float s = fmaxf(fmaxf(c[0], c[1]), c[2]);
    unsigned u = fmap(s);
    unsigned long long key = ((unsigned long long)u << 32) | (unsigned)(~(unsigned)i);
    g_keys[b][i] = key;
    atomicAdd(&g_hist[b][u >> 16], 1u);
}

// ---------------- kernel 2: histogram cutoff bin for top-1024 ----------------
__global__ void k_cut() {
    int b = blockIdx.x, t = threadIdx.x;  // blockDim = 1024
    __shared__ int sh[1024];
    int base = 65535 - t * 64;
    int p = 0;
    for (int k = 0; k < 64; k++) p += (int)g_hist[b][base - k];
    sh[t] = p;
    __syncthreads();
    for (int o = 1; o < 1024; o <<= 1) {
        int v = (t >= o) ? sh[t - o] : 0;
        __syncthreads();
        sh[t] += v;
        __syncthreads();
    }
    int incl = sh[t], excl = incl - p;
    if (excl < NPRE && incl >= NPRE) {
        int cum = excl;
        for (int k = 0; k < 64; k++) {
            cum += (int)g_hist[b][base - k];
            if (cum >= NPRE) { g_cut[b] = base - k; break; }
        }
    }
}

// ---------------- kernel 3: compact candidates ----------------
__global__ void k_compact() {
    int t = blockIdx.x * blockDim.x + threadIdx.x;
    if (t >= BATCH * NB) return;
    int b = t >> 14, i = t & (NB - 1);
    unsigned long long key = g_keys[b][i];
    int bin = (int)(unsigned)(key >> 48);
    if (bin >= g_cut[b]) {
        int p = atomicAdd(&g_candCnt[b], 1);
        if (p < 8192) g_cand[b][p] = key;
    }
}

// ---------------- kernel 4: sort candidates (descending), top-1024 ----------------
template <int N>
__device__ void bitonic_desc(unsigned long long* arr, int t) {
    for (int size = 2; size <= N; size <<= 1) {
        for (int stride = size >> 1; stride > 0; stride >>= 1) {
            __syncthreads();
            for (int q = t; q < N / 2; q += 1024) {
                int i = ((q & ~(stride - 1)) << 1) | (q & (stride - 1));
                int j = i + stride;
                bool desc = ((i & size) == 0);
                unsigned long long a = arr[i], c = arr[j];
                if (desc ? (a < c) : (a > c)) { arr[i] = c; arr[j] = a; }
            }
        }
    }
    __syncthreads();
}

__global__ void k_sorttop() {
    __shared__ unsigned long long arr[4096];   // 32 KB
    int b = blockIdx.x, t = threadIdx.x;       // blockDim = 1024
    int cnt = g_candCnt[b]; if (cnt > 4096) cnt = 4096;
    if (cnt <= 2048) {
        for (int i = t; i < 2048; i += 1024) arr[i] = (i < cnt) ? g_cand[b][i] : 0ULL;
        bitonic_desc<2048>(arr, t);
    } else {
        for (int i = t; i < 4096; i += 1024) arr[i] = (i < cnt) ? g_cand[b][i] : 0ULL;
        bitonic_desc<4096>(arr, t);
    }
    g_topidx[b][t] = (int)(~(unsigned)(arr[t] & 0xFFFFFFFFULL));
}

// ---------------- kernel 5: BEV geometry for selected ----------------
__global__ void k_bev(const float* __restrict__ boxes) {
    int t = blockIdx.x * blockDim.x + threadIdx.x;
    if (t >= BATCH * NPRE) return;
    int b = t >> 10, k = t & (NPRE - 1);
    int sel = g_topidx[b][k];
    const float* p = boxes + (size_t)(b * NB + sel) * 7;
    float x = p[0], y = p[1], dx = p[3], dy = p[4], ry = p[6];
    float c = (float)cos((double)ry);
    float s = (float)sin((double)ry);
    float* o = g_bev[b][k];
    o[0] = x; o[1] = y; o[2] = dx; o[3] = dy; o[4] = c; o[5] = s;
    const float offx[4] = { 0.5f, -0.5f, -0.5f,  0.5f };
    const float offy[4] = { 0.5f,  0.5f, -0.5f, -0.5f };
#pragma unroll
    for (int q = 0; q < 4; q++) {
        float lx = dx * offx[q], ly = dy * offy[q];
        o[6 + q]  = x + lx * c - ly * s;
        o[10 + q] = y + lx * s + ly * c;
    }
    o[14] = dx * dy;
    o[15] = 0.5f * sqrtf(dx * dx + dy * dy);
}

// ---------------- faithful pairwise IoU, register-only (sorting network) ----
__device__ float pair_iou(const float* __restrict__ A, const float* __restrict__ B) {
    float ax[4], ay[4], bx[4], by[4];
#pragma unroll
    for (int k = 0; k < 4; k++) { ax[k] = A[6 + k]; ay[k] = A[10 + k]; bx[k] = B[6 + k]; by[k] = B[10 + k]; }
    float dax[4], day[4], dbx[4], dby[4];
#pragma unroll
    for (int k = 0; k < 4; k++) {
        dax[k] = ax[(k + 1) & 3] - ax[k];  day[k] = ay[(k + 1) & 3] - ay[k];
        dbx[k] = bx[(k + 1) & 3] - bx[k];  dby[k] = by[(k + 1) & 3] - by[k];
    }
    float P[32], Q[32], ANG[32];
    bool mk[24];
#pragma unroll
    for (int p = 0; p < 4; p++) {
#pragma unroll
        for (int q = 0; q < 4; q++) {
            int id = p * 4 + q;
            float den = dax[p] * dby[q] - day[p] * dbx[q];
            float ddx = bx[q] - ax[p], ddy = by[q] - ay[p];
            bool nz = fabsf(den) > 1e-8f;
            float dens = nz ? den : 1.0f;
            float tt = (ddx * dby[q] - ddy * dbx[q]) / dens;
            float uu = (ddx * day[p] - ddy * dax[p]) / dens;
            mk[id] = nz && tt >= 0.f && tt <= 1.f && uu >= 0.f && uu <= 1.f;
            P[id] = ax[p] + tt * dax[p];
            Q[id] = ay[p] + tt * day[p];
        }
    }
    float Bx = B[0], By = B[1], Bdx = B[2], Bdy = B[3], Bc = B[4], Bs = B[5];
    float Ax = A[0], Ay = A[1], Adx = A[2], Ady = A[3], Ac = A[4], As = A[5];
#pragma unroll
    for (int k = 0; k < 4; k++) {
        P[16 + k] = ax[k]; Q[16 + k] = ay[k];
        float rx = ax[k] - Bx, ry = ay[k] - By;
        float qx = rx * Bc + ry * Bs, qy = -rx * Bs + ry * Bc;
        mk[16 + k] = (fabsf(qx) <= Bdx * 0.5f + 1e-5f) && (fabsf(qy) <= Bdy * 0.5f + 1e-5f);
        P[20 + k] = bx[k]; Q[20 + k] = by[k];
        float rx2 = bx[k] - Ax, ry2 = by[k] - Ay;
        float qx2 = rx2 * Ac + ry2 * As, qy2 = -rx2 * As + ry2 * Ac;
        mk[20 + k] = (fabsf(qx2) <= Adx * 0.5f + 1e-5f) && (fabsf(qy2) <= Ady * 0.5f + 1e-5f);
    }
    int cnt = 0; float sx = 0.f, sy = 0.f;
#pragma unroll
    for (int k = 0; k < 24; k++) if (mk[k]) { cnt++; sx += P[k]; sy += Q[k]; }
    float inv = 1.0f / (float)(cnt > 0 ? cnt : 1);
    float cx = sx * inv, cy = sy * inv;
#pragma unroll
    for (int k = 0; k < 24; k++)
        ANG[k] = mk[k] ? atan2f(Q[k] - cy, P[k] - cx) : 1e9f;
#pragma unroll
    for (int k = 24; k < 32; k++) { ANG[k] = 1e30f; P[k] = 0.f; Q[k] = 0.f; }
    // fully-unrolled 32-wide bitonic sort ascending by ANG (registers only)
#pragma unroll
    for (int size = 2; size <= 32; size <<= 1) {
#pragma unroll
        for (int stride = size >> 1; stride > 0; stride >>= 1) {
#pragma unroll
            for (int i = 0; i < 32; i++) {
                int j = i ^ stride;
                if (j > i) {
                    bool up = ((i & size) == 0);
                    bool sw = up ? (ANG[i] > ANG[j]) : (ANG[i] < ANG[j]);
                    float t0 = sw ? ANG[j] : ANG[i]; float t1 = sw ? ANG[i] : ANG[j];
                    ANG[i] = t0; ANG[j] = t1;
                    float p0 = sw ? P[j] : P[i];     float p1 = sw ? P[i] : P[j];
                    P[i] = p0; P[j] = p1;
                    float q0 = sw ? Q[j] : Q[i];     float q1 = sw ? Q[i] : Q[j];
                    Q[i] = q0; Q[j] = q1;
                }
            }
        }
    }
    // first 24 sorted entries = the 24 real entries (pads are 1e30, largest);
    // first cnt of them are the active ones (masked are 1e9)
    float fx = P[0], fy = Q[0];
    float cr = 0.f;
#pragma unroll
    for (int k = 0; k < 24; k++) {
        int kn = (k + 1) % 24;
        float xk = (k  < cnt) ? P[k]  : fx;
        float yk = (k  < cnt) ? Q[k]  : fy;
        float xn = (kn < cnt) ? P[kn] : fx;
        float yn = (kn < cnt) ? Q[kn] : fy;
        cr += xk * yn - yk * xn;
    }
    float inter = 0.5f * fabsf(cr);
    return inter / fmaxf(A[14] + B[14] - inter, 1e-6f);
}

// ---------------- kernel 6: prune pairs into queue ----------------
__global__ void k_pairs() {
    int b = blockIdx.y;
    int g = blockIdx.x * blockDim.x + threadIdx.x;   // 0 .. 32767
    int i = g >> 5, w = g & 31;
    __shared__ float sx[NPRE], sy[NPRE], sa[NPRE], sr[NPRE];
    for (int k = threadIdx.x; k < NPRE; k += blockDim.x) {
        const float* bp = g_bev[b][k];
        sx[k] = bp[0]; sy[k] = bp[1]; sa[k] = bp[14]; sr[k] = bp[15];
    }
    __syncthreads();
    float xi = sx[i], yi = sy[i], ai = sa[i], ri = sr[i];
    for (int jj = 0; jj < 32; jj++) {
        int j = w * 32 + jj;
        if (j <= i) continue;
        float ddx = xi - sx[j], ddy = yi - sy[j];
        float rs = ri + sr[j] + 1e-3f;
        if (ddx * ddx + ddy * ddy >= rs * rs) continue;   // disjoint -> IoU 0
        float aj = sa[j];
        float amin = fminf(ai, aj), amax = fmaxf(ai, aj);
        if (amin <= 0.79f * amax) continue;               // IoU <= amin/amax < 0.8
        int p = atomicAdd(&g_pairCnt[b], 1);
        if (p < PAIR_CAP) g_pairs[b][p] = ((unsigned)i << 16) | (unsigned)j;
    }
}

// ---------------- kernel 7: exact IoU on surviving pairs ----------------
__global__ void k_iou() {
    int b = blockIdx.y;
    int t = blockIdx.x * blockDim.x + threadIdx.x;
    int cnt = g_pairCnt[b]; if (cnt > PAIR_CAP) cnt = PAIR_CAP;
    if (t >= cnt) return;
    unsigned pr = g_pairs[b][t];
    int i = (int)(pr >> 16), j = (int)(pr & 0xFFFFu);
    float iou = pair_iou(g_bev[b][i], g_bev[b][j]);
    if (iou > NMS_THRESH) atomicOr(&g_mask[b][i][j >> 5], 1u << (j & 31));
}

// ---------------- kernel 8: blocked greedy NMS (one warp per batch) -------
__global__ void k_nms() {
    int b = blockIdx.x;
    int lane = threadIdx.x;                // blockDim = 32; lane holds supp word `lane`
    unsigned supp = 0u;
    const unsigned* __restrict__ M = &g_mask[b][0][0];
    for (int c = 0; c < 32; c++) {
        // diagonal block words: all lanes load same address (broadcast), independent -> pipelined
        unsigned d[32];
#pragma unroll
        for (int k = 0; k < 32; k++) d[k] = M[(c * 32 + k) * 32 + c];
        unsigned cur = __shfl_sync(0xffffffffu, supp, c);
        // register-only serial chain (rows only set bits j>i, so processed bits are stable)
#pragma unroll
        for (int k = 0; k < 32; k++)
            cur |= ((cur >> k) & 1u) ? 0u : d[k];
        unsigned alive = ~cur;
        // alive rows broadcast their full mask row into the distributed supp
#pragma unroll 4
        for (int k = 0; k < 32; k++)
            if ((alive >> k) & 1u) supp |= M[(c * 32 + k) * 32 + lane];
    }
    unsigned keep = ~supp;
    int cctn = __popc(keep);
    int incl = cctn;
    for (int o = 1; o < 32; o <<= 1) {
        int v = __shfl_up_sync(0xffffffffu, incl, o);
        if (lane >= o) incl += v;
    }
    int excl = incl - cctn;
    for (int s = lane; s < NPOST; s += 32) g_pos[b][s] = -1;
    __syncwarp();
    unsigned m = keep;
    int slot = excl;
    while (m) {
        if (slot >= NPOST) break;
        int bit = __ffs(m) - 1;
        g_pos[b][slot++] = lane * 32 + bit;
        m &= (m - 1);
    }
}

// ---------------- kernel 9: write outputs ----------------
// layout (float32): rois[2][512][7] | scores[2][512] | labels[2][512] | logits[2][512][3]
__global__ void k_out(const float* __restrict__ boxes, const float* __restrict__ cls,
                      float* __restrict__ out) {
    int t = blockIdx.x * blockDim.x + threadIdx.x;
    if (t >= BATCH * NPOST) return;
    int b = t >> 9, k = t & (NPOST - 1);
    int p = g_pos[b][k];
    float r0 = 0.f, r1 = 0.f, r2 = 0.f, r3 = 0.f, r4 = 0.f, r5 = 0.f, r6 = 0.f;
    float l0 = 0.f, l1 = 0.f, l2 = 0.f, score = 0.f, lab = 1.f;
    if (p >= 0) {
        int sel = g_topidx[b][p];
        const float* bp = boxes + (size_t)(b * NB + sel) * 7;
        r0 = bp[0]; r1 = bp[1]; r2 = bp[2]; r3 = bp[3]; r4 = bp[4]; r5 = bp[5]; r6 = bp[6];
        const float* cp = cls + (size_t)(b * NB + sel) * 3;
        l0 = cp[0]; l1 = cp[1]; l2 = cp[2];
        int a = 0; float best = l0;
        if (l1 > best) { best = l1; a = 1; }
        if (l2 > best) { best = l2; a = 2; }
        score = best; lab = (float)(a + 1);
    }
    int s = b * NPOST + k;
    float* ro = out + (size_t)s * 7;
    ro[0] = r0; ro[1] = r1; ro[2] = r2; ro[3] = r3; ro[4] = r4; ro[5] = r5; ro[6] = r6;
    out[BATCH * NPOST * 7 + s] = score;
    out[BATCH * NPOST * 8 + s] = lab;
    float* lo = out + BATCH * NPOST * 9 + (size_t)s * 3;
    lo[0] = l0; lo[1] = l1; lo[2] = l2;
}

// ---------------- launch ----------------
extern "C" void kernel_launch(void* const* d_in, const int* in_sizes, int n_in,
                              void* d_out, int out_size) {
    const float* boxes = (const float*)d_in[0];
    const float* cls   = (const float*)d_in[1];
    if (n_in >= 2 && in_sizes[0] == BATCH * NB * 3) {
        const float* tmp = boxes; boxes = cls; cls = tmp;
    }
    float* out = (float*)d_out;
    (void)out_size;

    k_zero   <<<(BATCH * 65536 + 255) / 256, 256>>>();
    k_keys   <<<(BATCH * NB + 255) / 256, 256>>>(cls);
    k_cut    <<<BATCH, 1024>>>();
    k_compact<<<(BATCH * NB + 255) / 256, 256>>>();
    k_sorttop<<<BATCH, 1024>>>();
    k_bev    <<<(BATCH * NPRE + 255) / 256, 256>>>(boxes);
    k_pairs  <<<dim3(128, BATCH), 256>>>();
    k_iou    <<<dim3(PAIR_CAP / 256, BATCH), 256>>>();
    k_nms    <<<BATCH, 32>>>();
    k_out    <<<(BATCH * NPOST + 255) / 256, 256>>>(boxes, cls, out);
}

// round 3
// speedup vs baseline: 4.1131x; 1.7239x over previous
#include <cuda_runtime.h>
#include <stdint.h>
#include <math.h>

#define NB    16384
#define NPRE  1024
#define NPOST 512
#define BATCH 2
#define NMS_THRESH 0.8f
#define NBINS 2048
#define QCAP  6144
#define GB_ROWS 64            // mask rows per block in k_mask

// ---------------- device scratch ----------------
__device__ int          g_topidx[BATCH][NPRE];
__device__ float        g_bev[BATCH][NPRE][16];
// per box: [0]x [1]y [2]dx [3]dy [4]cos [5]sin [6..9]cx [10..13]cy [14]area [15]radius
__device__ unsigned int g_mask[BATCH][NPRE][32];

// ---------------- helpers ----------------
__device__ __forceinline__ unsigned fmap(float f) {
    unsigned u = __float_as_uint(f);
    return u ^ ((u & 0x80000000u) ? 0xFFFFFFFFu : 0x80000000u);
}

// =====================================================================
// Kernel 1: top-1024 select (hist + sort) + BEV geometry.  grid=BATCH
// =====================================================================
__global__ void __launch_bounds__(1024, 1)
k_select(const float* __restrict__ cls, const float* __restrict__ boxes) {
    int b = blockIdx.x, t = threadIdx.x;
    __shared__ unsigned hist[NBINS];
    __shared__ unsigned cum[NBINS];
    __shared__ unsigned long long cand[2048];
    __shared__ int s_b1, s_chi, s_b2, s_usel2, s_cnt;

    for (int i = t; i < NBINS; i += 1024) hist[i] = 0u;
    if (t == 0) { s_usel2 = 0; s_cnt = 0; s_b2 = 0; }
    __syncthreads();

    const float* C = cls + (size_t)b * NB * 3;

    // pass 1: histogram of top-11 bits of mapped score
#pragma unroll 4
    for (int k = 0; k < 16; k++) {
        int e = t + k * 1024;
        float s = fmaxf(fmaxf(C[e * 3], C[e * 3 + 1]), C[e * 3 + 2]);
        atomicAdd(&hist[fmap(s) >> 21], 1u);
    }
    __syncthreads();

    // suffix scan (cum[i] = count of keys with bin >= i)
    for (int i = t; i < NBINS; i += 1024) cum[i] = hist[i];
    __syncthreads();
    for (int off = 1; off < NBINS; off <<= 1) {
        unsigned v0 = (t + off < NBINS) ? cum[t + off] : 0u;
        unsigned v1 = (t + 1024 + off < NBINS) ? cum[t + 1024 + off] : 0u;
        __syncthreads();
        cum[t] += v0; cum[t + 1024] += v1;
        __syncthreads();
    }
    for (int i = t; i < NBINS; i += 1024) {
        if (cum[i] >= NPRE && (i == NBINS - 1 || cum[i + 1] < NPRE)) {
            s_b1 = i; s_chi = (i == NBINS - 1) ? 0 : (int)cum[i + 1];
        }
    }
    __syncthreads();
    int b1 = s_b1, chi = s_chi;
    int cnt1 = (int)cum[b1] - chi;

    if (chi + cnt1 > 2048) {      // rare: refine boundary bin by next 11 bits
        for (int i = t; i < NBINS; i += 1024) hist[i] = 0u;
        if (t == 0) s_usel2 = 1;
        __syncthreads();
        for (int k = 0; k < 16; k++) {
            int e = t + k * 1024;
            float s = fmaxf(fmaxf(C[e * 3], C[e * 3 + 1]), C[e * 3 + 2]);
            unsigned u = fmap(s);
            if ((int)(u >> 21) == b1) atomicAdd(&hist[(u >> 10) & 0x7FF], 1u);
        }
        __syncthreads();
        for (int i = t; i < NBINS; i += 1024) cum[i] = hist[i];
        __syncthreads();
        for (int off = 1; off < NBINS; off <<= 1) {
            unsigned v0 = (t + off < NBINS) ? cum[t + off] : 0u;
            unsigned v1 = (t + 1024 + off < NBINS) ? cum[t + 1024 + off] : 0u;
            __syncthreads();
            cum[t] += v0; cum[t + 1024] += v1;
            __syncthreads();
        }
        int target2 = NPRE - chi;
        for (int i = t; i < NBINS; i += 1024) {
            if ((int)cum[i] >= target2 && (i == NBINS - 1 || (int)cum[i + 1] < target2))
                s_b2 = i;
        }
        __syncthreads();
    }

    // compact candidates into smem
    for (int i = t; i < 2048; i += 1024) cand[i] = 0ULL;
    __syncthreads();
    int usel2 = s_usel2, b2 = s_b2;
#pragma unroll 4
    for (int k = 0; k < 16; k++) {
        int e = t + k * 1024;
        float s = fmaxf(fmaxf(C[e * 3], C[e * 3 + 1]), C[e * 3 + 2]);
        unsigned u = fmap(s);
        int bin = (int)(u >> 21);
        bool take = (bin > b1) ||
                    (bin == b1 && (!usel2 || (int)((u >> 10) & 0x7FF) >= b2));
        if (take) {
            int p = atomicAdd(&s_cnt, 1);
            if (p < 2048)
                cand[p] = ((unsigned long long)u << 32) | (unsigned)(~(unsigned)e);
        }
    }
    __syncthreads();

    // bitonic sort 2048 descending (1 CE per thread per pass)
    for (int size = 2; size <= 2048; size <<= 1) {
        for (int stride = size >> 1; stride > 0; stride >>= 1) {
            int i = ((t & ~(stride - 1)) << 1) | (t & (stride - 1));
            int j = i + stride;
            bool desc = ((i & size) == 0);
            unsigned long long a = cand[i], c = cand[j];
            if (desc ? (a < c) : (a > c)) { cand[i] = c; cand[j] = a; }
            __syncthreads();
        }
    }

    // top-1024: indices + BEV geometry
    if (t < NPRE) {
        int sel = (int)(~(unsigned)(cand[t] & 0xFFFFFFFFULL));
        g_topidx[b][t] = sel;
        const float* p = boxes + (size_t)(b * NB + sel) * 7;
        float x = p[0], y = p[1], dx = p[3], dy = p[4], ry = p[6];
        float c = (float)cos((double)ry);
        float s = (float)sin((double)ry);
        float* o = g_bev[b][t];
        o[0] = x; o[1] = y; o[2] = dx; o[3] = dy; o[4] = c; o[5] = s;
        const float offx[4] = { 0.5f, -0.5f, -0.5f,  0.5f };
        const float offy[4] = { 0.5f,  0.5f, -0.5f, -0.5f };
#pragma unroll
        for (int q = 0; q < 4; q++) {
            float lx = dx * offx[q], ly = dy * offy[q];
            o[6 + q]  = x + lx * c - ly * s;
            o[10 + q] = y + lx * s + ly * c;
        }
        o[14] = dx * dy;
        o[15] = 0.5f * sqrtf(dx * dx + dy * dy);
    }
}

// ---------------- faithful pairwise IoU (register-only) ----------------
__device__ float pair_iou(const float* __restrict__ A, const float* __restrict__ B) {
    float ax[4], ay[4], bx[4], by[4];
#pragma unroll
    for (int k = 0; k < 4; k++) { ax[k] = A[6 + k]; ay[k] = A[10 + k]; bx[k] = B[6 + k]; by[k] = B[10 + k]; }
    float dax[4], day[4], dbx[4], dby[4];
#pragma unroll
    for (int k = 0; k < 4; k++) {
        dax[k] = ax[(k + 1) & 3] - ax[k];  day[k] = ay[(k + 1) & 3] - ay[k];
        dbx[k] = bx[(k + 1) & 3] - bx[k];  dby[k] = by[(k + 1) & 3] - by[k];
    }
    float P[32], Q[32], ANG[32];
    bool mk[24];
#pragma unroll
    for (int p = 0; p < 4; p++) {
#pragma unroll
        for (int q = 0; q < 4; q++) {
            int id = p * 4 + q;
            float den = dax[p] * dby[q] - day[p] * dbx[q];
            float ddx = bx[q] - ax[p], ddy = by[q] - ay[p];
            bool nz = fabsf(den) > 1e-8f;
            float dens = nz ? den : 1.0f;
            float tt = (ddx * dby[q] - ddy * dbx[q]) / dens;
            float uu = (ddx * day[p] - ddy * dax[p]) / dens;
            mk[id] = nz && tt >= 0.f && tt <= 1.f && uu >= 0.f && uu <= 1.f;
            P[id] = ax[p] + tt * dax[p];
            Q[id] = ay[p] + tt * day[p];
        }
    }
    float Bx = B[0], By = B[1], Bdx = B[2], Bdy = B[3], Bc = B[4], Bs = B[5];
    float Ax = A[0], Ay = A[1], Adx = A[2], Ady = A[3], Ac = A[4], As = A[5];
#pragma unroll
    for (int k = 0; k < 4; k++) {
        P[16 + k] = ax[k]; Q[16 + k] = ay[k];
        float rx = ax[k] - Bx, ry = ay[k] - By;
        float qx = rx * Bc + ry * Bs, qy = -rx * Bs + ry * Bc;
        mk[16 + k] = (fabsf(qx) <= Bdx * 0.5f + 1e-5f) && (fabsf(qy) <= Bdy * 0.5f + 1e-5f);
        P[20 + k] = bx[k]; Q[20 + k] = by[k];
        float rx2 = bx[k] - Ax, ry2 = by[k] - Ay;
        float qx2 = rx2 * Ac + ry2 * As, qy2 = -rx2 * As + ry2 * Ac;
        mk[20 + k] = (fabsf(qx2) <= Adx * 0.5f + 1e-5f) && (fabsf(qy2) <= Ady * 0.5f + 1e-5f);
    }
    int cnt = 0; float sx = 0.f, sy = 0.f;
#pragma unroll
    for (int k = 0; k < 24; k++) if (mk[k]) { cnt++; sx += P[k]; sy += Q[k]; }
    float inv = 1.0f / (float)(cnt > 0 ? cnt : 1);
    float cx = sx * inv, cy = sy * inv;
#pragma unroll
    for (int k = 0; k < 24; k++)
        ANG[k] = mk[k] ? atan2f(Q[k] - cy, P[k] - cx) : 1e9f;
#pragma unroll
    for (int k = 24; k < 32; k++) { ANG[k] = 1e30f; P[k] = 0.f; Q[k] = 0.f; }
#pragma unroll
    for (int size = 2; size <= 32; size <<= 1) {
#pragma unroll
        for (int stride = size >> 1; stride > 0; stride >>= 1) {
#pragma unroll
            for (int i = 0; i < 32; i++) {
                int j = i ^ stride;
                if (j > i) {
                    bool up = ((i & size) == 0);
                    bool sw = up ? (ANG[i] > ANG[j]) : (ANG[i] < ANG[j]);
                    float t0 = sw ? ANG[j] : ANG[i]; float t1 = sw ? ANG[i] : ANG[j];
                    ANG[i] = t0; ANG[j] = t1;
                    float p0 = sw ? P[j] : P[i];     float p1 = sw ? P[i] : P[j];
                    P[i] = p0; P[j] = p1;
                    float q0 = sw ? Q[j] : Q[i];     float q1 = sw ? Q[i] : Q[j];
                    Q[i] = q0; Q[j] = q1;
                }
            }
        }
    }
    float fx = P[0], fy = Q[0];
    float cr = 0.f;
#pragma unroll
    for (int k = 0; k < 24; k++) {
        int kn = (k + 1) % 24;
        float xk = (k  < cnt) ? P[k]  : fx;
        float yk = (k  < cnt) ? Q[k]  : fy;
        float xn = (kn < cnt) ? P[kn] : fx;
        float yn = (kn < cnt) ? Q[kn] : fy;
        cr += xk * yn - yk * xn;
    }
    float inter = 0.5f * fabsf(cr);
    return inter / fmaxf(A[14] + B[14] - inter, 1e-6f);
}

// =====================================================================
// Kernel 2: fused prune + exact IoU -> suppression bitmask.
// grid = (NPRE/GB_ROWS, BATCH), block = 1024
// =====================================================================
__global__ void __launch_bounds__(1024, 1) k_mask() {
    int b = blockIdx.y, blk = blockIdx.x, t = threadIdx.x;
    int i0 = blk * GB_ROWS;
    __shared__ float sx[NPRE], sy[NPRE], sa[NPRE], sr[NPRE];
    __shared__ unsigned q[QCAP];
    __shared__ int qc;
    if (t == 0) qc = 0;
    for (int k = t; k < NPRE; k += 1024) {
        const float* bp = g_bev[b][k];
        sx[k] = bp[0]; sy[k] = bp[1]; sa[k] = bp[14]; sr[k] = bp[15];
    }
    // zero this block's strip of the mask (sole writer of these rows)
    for (int k = t; k < GB_ROWS * 32; k += 1024)
        ((unsigned*)g_mask[b][i0])[k] = 0u;
    __syncthreads();

    int j = t;     // column handled by this thread
    float xj = sx[j], yj = sy[j], aj = sa[j], rj = sr[j];
    for (int r = 0; r < GB_ROWS; r++) {
        int i = i0 + r;
        if (j > i) {
            float ddx = sx[i] - xj, ddy = sy[i] - yj;
            float rs = sr[i] + rj + 1e-3f;
            if (ddx * ddx + ddy * ddy < rs * rs) {
                float amin = fminf(sa[i], aj), amax = fmaxf(sa[i], aj);
                if (amin > 0.79f * amax) {
                    int p = atomicAdd(&qc, 1);
                    if (p < QCAP) q[p] = ((unsigned)i << 16) | (unsigned)j;
                    else {  // overflow fallback (never expected): inline
                        float iou = pair_iou(g_bev[b][i], g_bev[b][j]);
                        if (iou > NMS_THRESH)
                            atomicOr(&g_mask[b][i][j >> 5], 1u << (j & 31));
                    }
                }
            }
        }
    }
    __syncthreads();
    int n = min(qc, QCAP);
    for (int p = t; p < n; p += 1024) {
        unsigned pr = q[p];
        int i = (int)(pr >> 16), jj = (int)(pr & 0xFFFFu);
        float iou = pair_iou(g_bev[b][i], g_bev[b][jj]);
        if (iou > NMS_THRESH) atomicOr(&g_mask[b][i][jj >> 5], 1u << (jj & 31));
    }
}

// =====================================================================
// Kernel 3: greedy NMS with sparsity skips + output write.  grid=BATCH
// out layout: rois[2][512][7] | scores[2][512] | labels[2][512] | logits[2][512][3]
// =====================================================================
__global__ void __launch_bounds__(1024, 1)
k_nmsout(const float* __restrict__ boxes, const float* __restrict__ cls,
         float* __restrict__ out) {
    int b = blockIdx.x, t = threadIdx.x;
    __shared__ unsigned rowAny[32];
    __shared__ int pos[NPOST];
    if (t < 32) rowAny[t] = 0u;
    for (int k = t; k < NPOST; k += 1024) pos[k] = -1;
    __syncthreads();

    // warm mask into L1 + build row-nonzero bitmap (thread t = row t)
    {
        const unsigned* R = g_mask[b][t];
        unsigned any = 0u;
#pragma unroll
        for (int w = 0; w < 32; w++) any |= __ldg(&R[w]);
        if (any) atomicOr(&rowAny[t >> 5], 1u << (t & 31));
    }
    __syncthreads();

    if (t < 32) {
        int lane = t;
        unsigned supp = 0u;
        const unsigned* __restrict__ M = &g_mask[b][0][0];
        for (int c = 0; c < 32; c++) {
            unsigned ra = rowAny[c];
            unsigned cur = __shfl_sync(0xffffffffu, supp, c);
            if (ra & ~cur) {
                unsigned d[32];
#pragma unroll
                for (int k = 0; k < 32; k++)
                    d[k] = ((ra >> k) & 1u) ? __ldg(&M[(c * 32 + k) * 32 + c]) : 0u;
#pragma unroll
                for (int k = 0; k < 32; k++)
                    cur |= ((cur >> k) & 1u) ? 0u : d[k];
                unsigned act = ~cur & ra;
                while (act) {
                    int k = __ffs(act) - 1;
                    supp |= __ldg(&M[(c * 32 + k) * 32 + lane]);
                    act &= act - 1;
                }
            }
        }
        unsigned keep = ~supp;
        int cc = __popc(keep);
        int incl = cc;
        for (int o = 1; o < 32; o <<= 1) {
            int v = __shfl_up_sync(0xffffffffu, incl, o);
            if (lane >= o) incl += v;
        }
        int excl = incl - cc;
        __syncwarp();
        unsigned m = keep;
        int slot = excl;
        while (m) {
            if (slot >= NPOST) break;
            int bit = __ffs(m) - 1;
            pos[slot++] = lane * 32 + bit;
            m &= (m - 1);
        }
    }
    __syncthreads();

    if (t < NPOST) {
        int p = pos[t];
        float r0 = 0.f, r1 = 0.f, r2 = 0.f, r3 = 0.f, r4 = 0.f, r5 = 0.f, r6 = 0.f;
        float l0 = 0.f, l1 = 0.f, l2 = 0.f, score = 0.f, lab = 1.f;
        if (p >= 0) {
            int sel = g_topidx[b][p];
            const float* bp = boxes + (size_t)(b * NB + sel) * 7;
            r0 = bp[0]; r1 = bp[1]; r2 = bp[2]; r3 = bp[3]; r4 = bp[4]; r5 = bp[5]; r6 = bp[6];
            const float* cp = cls + (size_t)(b * NB + sel) * 3;
            l0 = cp[0]; l1 = cp[1]; l2 = cp[2];
            int a = 0; float best = l0;
            if (l1 > best) { best = l1; a = 1; }
            if (l2 > best) { best = l2; a = 2; }
            score = best; lab = (float)(a + 1);
        }
        int s = b * NPOST + t;
        float* ro = out + (size_t)s * 7;
        ro[0] = r0; ro[1] = r1; ro[2] = r2; ro[3] = r3; ro[4] = r4; ro[5] = r5; ro[6] = r6;
        out[BATCH * NPOST * 7 + s] = score;
        out[BATCH * NPOST * 8 + s] = lab;
        float* lo = out + BATCH * NPOST * 9 + (size_t)s * 3;
        lo[0] = l0; lo[1] = l1; lo[2] = l2;
    }
}

// ---------------- launch ----------------
extern "C" void kernel_launch(void* const* d_in, const int* in_sizes, int n_in,
                              void* d_out, int out_size) {
    const float* boxes = (const float*)d_in[0];
    const float* cls   = (const float*)d_in[1];
    if (n_in >= 2 && in_sizes[0] == BATCH * NB * 3) {
        const float* tmp = boxes; boxes = cls; cls = tmp;
    }
    float* out = (float*)d_out;
    (void)out_size;

    k_select<<<BATCH, 1024>>>(cls, boxes);
    k_mask  <<<dim3(NPRE / GB_ROWS, BATCH), 1024>>>();
    k_nmsout<<<BATCH, 1024>>>(boxes, cls, out);
}

// round 6
// speedup vs baseline: 4.1322x; 1.0047x over previous
#include <cuda_runtime.h>
#include <stdint.h>
#include <math.h>

#define NB    16384
#define NPRE  1024
#define NPOST 512
#define BATCH 2
#define NMS_THRESH 0.8f
#define NBINS 2048
#define QCAP  6144
#define GB_ROWS 64            // mask rows per block in k_mask

// ---------------- device scratch ----------------
__device__ int          g_topidx[BATCH][NPRE];
__device__ float        g_bev[BATCH][NPRE][16];
// per box: [0]x [1]y [2]dx [3]dy [4]cos [5]sin [6..9]cx [10..13]cy [14]area [15]radius
__device__ float4       g_prune[BATCH][NPRE];     // x, y, area, radius
__device__ unsigned int g_mask[BATCH][NPRE][32];
__device__ unsigned int g_rowAny[BATCH][32];

// ---------------- helpers ----------------
__device__ __forceinline__ unsigned fmap(float f) {
    unsigned u = __float_as_uint(f);
    return u ^ ((u & 0x80000000u) ? 0xFFFFFFFFu : 0x80000000u);
}

__device__ __forceinline__ unsigned long long ce_shfl(unsigned long long v, int i,
                                                      int stride, int size) {
    unsigned long long p = __shfl_xor_sync(0xffffffffu, v, stride);
    bool descB = ((i & size) == 0);
    bool lower = ((i & stride) == 0);
    bool keepMax = (descB == lower);
    unsigned long long mx = v > p ? v : p, mn = v > p ? p : v;
    return keepMax ? mx : mn;
}

// =====================================================================
// Kernel 1: top-1024 select + BEV geometry.  grid=BATCH, block=1024
// =====================================================================
__global__ void __launch_bounds__(1024, 1)
k_select(const float* __restrict__ cls, const float* __restrict__ boxes) {
    int b = blockIdx.x, t = threadIdx.x;
    __shared__ unsigned long long candA[2048];   // 16 KB
    __shared__ unsigned long long candB[2048];   // 16 KB (aliased: hist+cum early)
    unsigned* hist = (unsigned*)candB;           // [0..2048)
    unsigned* cum  = ((unsigned*)candB) + 2048;  // [2048..4096)
    __shared__ int s_b1, s_chi, s_b2, s_usel2, s_cnt;

    // init
    candA[t] = (unsigned long long)t;            // pad keys (unique, tiny)
    candA[t + 1024] = (unsigned long long)(t + 1024);
    hist[t] = 0u; hist[t + 1024] = 0u;
    if (t == 0) { s_usel2 = 0; s_cnt = 0; s_b2 = 0; }
    if (t < 32) g_rowAny[b][t] = 0u;
    __syncthreads();

    const float* C = cls + (size_t)b * NB * 3;

    // single pass: scores -> u (registers) + histogram of top-11 bits
    unsigned myu[16];
#pragma unroll 4
    for (int k = 0; k < 16; k++) {
        int e = t + k * 1024;
        float s = fmaxf(fmaxf(C[e * 3], C[e * 3 + 1]), C[e * 3 + 2]);
        unsigned u = fmap(s);
        myu[k] = u;
        atomicAdd(&hist[u >> 21], 1u);
    }
    __syncthreads();

    // suffix scan: cum[i] = count of keys with bin >= i
    cum[t] = hist[t]; cum[t + 1024] = hist[t + 1024];
    __syncthreads();
    for (int off = 1; off < NBINS; off <<= 1) {
        unsigned v0 = (t + off < NBINS) ? cum[t + off] : 0u;
        unsigned v1 = (t + 1024 + off < NBINS) ? cum[t + 1024 + off] : 0u;
        __syncthreads();
        cum[t] += v0; cum[t + 1024] += v1;
        __syncthreads();
    }
    for (int i = t; i < NBINS; i += 1024) {
        if (cum[i] >= NPRE && (i == NBINS - 1 || cum[i + 1] < NPRE)) {
            s_b1 = i; s_chi = (i == NBINS - 1) ? 0 : (int)cum[i + 1];
        }
    }
    __syncthreads();
    int b1 = s_b1, chi = s_chi;
    int cnt1 = (int)cum[b1] - chi;

    if (chi + cnt1 > 2048) {      // rare: refine boundary bin by next 11 bits
        __syncthreads();
        hist[t] = 0u; hist[t + 1024] = 0u;
        if (t == 0) s_usel2 = 1;
        __syncthreads();
#pragma unroll 4
        for (int k = 0; k < 16; k++) {
            unsigned u = myu[k];
            if ((int)(u >> 21) == b1) atomicAdd(&hist[(u >> 10) & 0x7FF], 1u);
        }
        __syncthreads();
        cum[t] = hist[t]; cum[t + 1024] = hist[t + 1024];
        __syncthreads();
        for (int off = 1; off < NBINS; off <<= 1) {
            unsigned v0 = (t + off < NBINS) ? cum[t + off] : 0u;
            unsigned v1 = (t + 1024 + off < NBINS) ? cum[t + 1024 + off] : 0u;
            __syncthreads();
            cum[t] += v0; cum[t + 1024] += v1;
            __syncthreads();
        }
        int target2 = NPRE - chi;
        for (int i = t; i < NBINS; i += 1024) {
            if ((int)cum[i] >= target2 && (i == NBINS - 1 || (int)cum[i + 1] < target2))
                s_b2 = i;
        }
        __syncthreads();
    }

    // compact candidates into candA
    int usel2 = s_usel2, b2 = s_b2;
#pragma unroll 4
    for (int k = 0; k < 16; k++) {
        unsigned u = myu[k];
        int bin = (int)(u >> 21);
        bool take = (bin > b1) ||
                    (bin == b1 && (!usel2 || (int)((u >> 10) & 0x7FF) >= b2));
        if (take) {
            int p = atomicAdd(&s_cnt, 1);
            if (p < 2048) {
                int e = t + k * 1024;
                candA[p] = ((unsigned long long)u << 32) | (unsigned)(~(unsigned)e);
            }
        }
    }
    __syncthreads();

    // ---- sort phase 1: each warp sorts its 64-key chunk in registers (desc) ----
    {
        int w = t >> 5, l = t & 31;
        unsigned long long v0 = candA[w * 64 + l];
        unsigned long long v1 = candA[w * 64 + 32 + l];
        int i0 = l, i1 = l + 32;
#pragma unroll
        for (int size = 2; size <= 64; size <<= 1) {
#pragma unroll
            for (int stride = size >> 1; stride > 0; stride >>= 1) {
                if (stride == 32) {
                    bool descB = ((i0 & size) == 0);
                    unsigned long long mx = v0 > v1 ? v0 : v1;
                    unsigned long long mn = v0 > v1 ? v1 : v0;
                    v0 = descB ? mx : mn; v1 = descB ? mn : mx;
                } else {
                    v0 = ce_shfl(v0, i0, stride, size);
                    v1 = ce_shfl(v1, i1, stride, size);
                }
            }
        }
        candA[w * 64 + l] = v0;
        candA[w * 64 + 32 + l] = v1;
    }
    __syncthreads();

    // ---- sort phase 2: 5 merge rounds via binary search (32 runs -> 1) ----
    {
        unsigned long long* src = candA;
        unsigned long long* dst = candB;
#pragma unroll
        for (int r = 0; r < 5; r++) {
            int L = 64 << r;
#pragma unroll
            for (int h = 0; h < 2; h++) {
                int p = t + h * 1024;
                unsigned long long key = src[p];
                bool first = ((p & L) == 0);
                int pairBase = p & ~(2 * L - 1);
                int idxInRun = p & (L - 1);
                int otherBase = pairBase + (first ? L : 0);
                int lo = 0, hi = L;
                while (lo < hi) {
                    int mid = (lo + hi) >> 1;
                    if (src[otherBase + mid] > key) lo = mid + 1; else hi = mid;
                }
                dst[pairBase + idxInRun + lo] = key;
            }
            __syncthreads();
            unsigned long long* tmp = src; src = dst; dst = tmp;
        }
        // 5 rounds: final sorted data in candB (src now points at it)
    }

    // ---- top-1024: indices + BEV geometry + prune vector ----
    if (t < NPRE) {
        int sel = (int)(~(unsigned)(candB[t] & 0xFFFFFFFFULL));
        g_topidx[b][t] = sel;
        const float* p = boxes + (size_t)(b * NB + sel) * 7;
        float x = p[0], y = p[1], dx = p[3], dy = p[4], ry = p[6];
        float c = (float)cos((double)ry);
        float s = (float)sin((double)ry);
        float* o = g_bev[b][t];
        o[0] = x; o[1] = y; o[2] = dx; o[3] = dy; o[4] = c; o[5] = s;
        const float offx[4] = { 0.5f, -0.5f, -0.5f,  0.5f };
        const float offy[4] = { 0.5f,  0.5f, -0.5f, -0.5f };
#pragma unroll
        for (int q = 0; q < 4; q++) {
            float lx = dx * offx[q], ly = dy * offy[q];
            o[6 + q]  = x + lx * c - ly * s;
            o[10 + q] = y + lx * s + ly * c;
        }
        float area = dx * dy;
        float rad  = 0.5f * sqrtf(dx * dx + dy * dy);
        o[14] = area; o[15] = rad;
        g_prune[b][t] = make_float4(x, y, area, rad);
    }
}

// ---------------- faithful pairwise IoU (register-only) ----------------
__device__ float pair_iou(const float* __restrict__ A, const float* __restrict__ B) {
    float ax[4], ay[4], bx[4], by[4];
#pragma unroll
    for (int k = 0; k < 4; k++) { ax[k] = A[6 + k]; ay[k] = A[10 + k]; bx[k] = B[6 + k]; by[k] = B[10 + k]; }
    float dax[4], day[4], dbx[4], dby[4];
#pragma unroll
    for (int k = 0; k < 4; k++) {
        dax[k] = ax[(k + 1) & 3] - ax[k];  day[k] = ay[(k + 1) & 3] - ay[k];
        dbx[k] = bx[(k + 1) & 3] - bx[k];  dby[k] = by[(k + 1) & 3] - by[k];
    }
    float P[32], Q[32], ANG[32];
    bool mk[24];
#pragma unroll
    for (int p = 0; p < 4; p++) {
#pragma unroll
        for (int q = 0; q < 4; q++) {
            int id = p * 4 + q;
            float den = dax[p] * dby[q] - day[p] * dbx[q];
            float ddx = bx[q] - ax[p], ddy = by[q] - ay[p];
            bool nz = fabsf(den) > 1e-8f;
            float dens = nz ? den : 1.0f;
            float tt = (ddx * dby[q] - ddy * dbx[q]) / dens;
            float uu = (ddx * day[p] - ddy * dax[p]) / dens;
            mk[id] = nz && tt >= 0.f && tt <= 1.f && uu >= 0.f && uu <= 1.f;
            P[id] = ax[p] + tt * dax[p];
            Q[id] = ay[p] + tt * day[p];
        }
    }
    float Bx = B[0], By = B[1], Bdx = B[2], Bdy = B[3], Bc = B[4], Bs = B[5];
    float Ax = A[0], Ay = A[1], Adx = A[2], Ady = A[3], Ac = A[4], As = A[5];
#pragma unroll
    for (int k = 0; k < 4; k++) {
        P[16 + k] = ax[k]; Q[16 + k] = ay[k];
        float rx = ax[k] - Bx, ry = ay[k] - By;
        float qx = rx * Bc + ry * Bs, qy = -rx * Bs + ry * Bc;
        mk[16 + k] = (fabsf(qx) <= Bdx * 0.5f + 1e-5f) && (fabsf(qy) <= Bdy * 0.5f + 1e-5f);
        P[20 + k] = bx[k]; Q[20 + k] = by[k];
        float rx2 = bx[k] - Ax, ry2 = by[k] - Ay;
        float qx2 = rx2 * Ac + ry2 * As, qy2 = -rx2 * As + ry2 * Ac;
        mk[20 + k] = (fabsf(qx2) <= Adx * 0.5f + 1e-5f) && (fabsf(qy2) <= Ady * 0.5f + 1e-5f);
    }
    int cnt = 0; float sx = 0.f, sy = 0.f;
#pragma unroll
    for (int k = 0; k < 24; k++) if (mk[k]) { cnt++; sx += P[k]; sy += Q[k]; }
    float inv = 1.0f / (float)(cnt > 0 ? cnt : 1);
    float cx = sx * inv, cy = sy * inv;
#pragma unroll
    for (int k = 0; k < 24; k++)
        ANG[k] = mk[k] ? atan2f(Q[k] - cy, P[k] - cx) : 1e9f;
#pragma unroll
    for (int k = 24; k < 32; k++) { ANG[k] = 1e30f; P[k] = 0.f; Q[k] = 0.f; }
#pragma unroll
    for (int size = 2; size <= 32; size <<= 1) {
#pragma unroll
        for (int stride = size >> 1; stride > 0; stride >>= 1) {
#pragma unroll
            for (int i = 0; i < 32; i++) {
                int j = i ^ stride;
                if (j > i) {
                    bool up = ((i & size) == 0);
                    bool sw = up ? (ANG[i] > ANG[j]) : (ANG[i] < ANG[j]);
                    float t0 = sw ? ANG[j] : ANG[i]; float t1 = sw ? ANG[i] : ANG[j];
                    ANG[i] = t0; ANG[j] = t1;
                    float p0 = sw ? P[j] : P[i];     float p1 = sw ? P[i] : P[j];
                    P[i] = p0; P[j] = p1;
                    float q0 = sw ? Q[j] : Q[i];     float q1 = sw ? Q[i] : Q[j];
                    Q[i] = q0; Q[j] = q1;
                }
            }
        }
    }
    float fx = P[0], fy = Q[0];
    float cr = 0.f;
#pragma unroll
    for (int k = 0; k < 24; k++) {
        int kn = (k + 1) % 24;
        float xk = (k  < cnt) ? P[k]  : fx;
        float yk = (k  < cnt) ? Q[k]  : fy;
        float xn = (kn < cnt) ? P[kn] : fx;
        float yn = (kn < cnt) ? Q[kn] : fy;
        cr += xk * yn - yk * xn;
    }
    float inter = 0.5f * fabsf(cr);
    return inter / fmaxf(A[14] + B[14] - inter, 1e-6f);
}

// =====================================================================
// Kernel 2: fused prune + exact IoU -> suppression bitmask + rowAny.
// grid = (NPRE/GB_ROWS, BATCH), block = 1024
// =====================================================================
__global__ void __launch_bounds__(1024, 1) k_mask() {
    int b = blockIdx.y, blk = blockIdx.x, t = threadIdx.x;
    int i0 = blk * GB_ROWS;
    __shared__ float4 spr[NPRE];           // 16 KB
    __shared__ unsigned q[QCAP];           // 24 KB
    __shared__ int qc;
    if (t == 0) qc = 0;
    spr[t] = g_prune[b][t];
    // zero this block's strip of the mask (sole writer of these rows)
    for (int k = t; k < GB_ROWS * 32; k += 1024)
        ((unsigned*)g_mask[b][i0])[k] = 0u;
    __syncthreads();

    int j = t;     // column handled by this thread
    float4 pj = spr[j];
    for (int r = 0; r < GB_ROWS; r++) {
        int i = i0 + r;
        if (j > i) {
            float4 pi = spr[i];
            float ddx = pi.x - pj.x, ddy = pi.y - pj.y;
            float rs = pi.w + pj.w + 1e-3f;
            if (ddx * ddx + ddy * ddy < rs * rs) {
                float amin = fminf(pi.z, pj.z), amax = fmaxf(pi.z, pj.z);
                if (amin > 0.79f * amax) {
                    int p = atomicAdd(&qc, 1);
                    if (p < QCAP) q[p] = ((unsigned)i << 16) | (unsigned)j;
                    else {  // overflow fallback (never expected)
                        float iou = pair_iou(g_bev[b][i], g_bev[b][j]);
                        if (iou > NMS_THRESH)
                            atomicOr(&g_mask[b][i][j >> 5], 1u << (j & 31));
                    }
                }
            }
        }
    }
    __syncthreads();
    int n = min(qc, QCAP);
    for (int p = t; p < n; p += 1024) {
        unsigned pr = q[p];
        int i = (int)(pr >> 16), jj = (int)(pr & 0xFFFFu);
        float iou = pair_iou(g_bev[b][i], g_bev[b][jj]);
        if (iou > NMS_THRESH) atomicOr(&g_mask[b][i][jj >> 5], 1u << (jj & 31));
    }
    __syncthreads();
    // rowAny for this strip: warp per row, 2 sweeps of 32 rows
    {
        int lane = t & 31;
#pragma unroll
        for (int sweep = 0; sweep < 2; sweep++) {
            int row = i0 + sweep * 32 + (t >> 5);
            unsigned val = g_mask[b][row][lane];
            bool any = __any_sync(0xffffffffu, val != 0u);
            if (lane == 0 && any)
                atomicOr(&g_rowAny[b][row >> 5], 1u << (row & 31));
        }
    }
}

// =====================================================================
// Kernel 3: greedy NMS with sparsity skips + output write.  grid=BATCH
// out layout: rois[2][512][7] | scores[2][512] | labels[2][512] | logits[2][512][3]
// =====================================================================
__global__ void __launch_bounds__(512, 1)
k_nmsout(const float* __restrict__ boxes, const float* __restrict__ cls,
         float* __restrict__ out) {
    int b = blockIdx.x, t = threadIdx.x;
    __shared__ unsigned s_rowAny[32];
    __shared__ int pos[NPOST];
    if (t < 32) s_rowAny[t] = g_rowAny[b][t];
    pos[t] = -1;
    __syncthreads();

    if (t < 32) {
        int lane = t;
        unsigned supp = 0u;
        const unsigned* __restrict__ M = &g_mask[b][0][0];
        for (int c = 0; c < 32; c++) {
            unsigned ra = s_rowAny[c];
            unsigned cur = __shfl_sync(0xffffffffu, supp, c);
            if (ra & ~cur) {
                unsigned d[32];
#pragma unroll
                for (int k = 0; k < 32; k++)
                    d[k] = ((ra >> k) & 1u) ? __ldg(&M[(c * 32 + k) * 32 + c]) : 0u;
#pragma unroll
                for (int k = 0; k < 32; k++)
                    cur |= ((cur >> k) & 1u) ? 0u : d[k];
                unsigned act = ~cur & ra;
                while (act) {
                    int k = __ffs(act) - 1;
                    supp |= __ldg(&M[(c * 32 + k) * 32 + lane]);
                    act &= act - 1;
                }
            }
        }
        unsigned keep = ~supp;
        int cc = __popc(keep);
        int incl = cc;
        for (int o = 1; o < 32; o <<= 1) {
            int v = __shfl_up_sync(0xffffffffu, incl, o);
            if (lane >= o) incl += v;
        }
        int excl = incl - cc;
        __syncwarp();
        unsigned m = keep;
        int slot = excl;
        while (m) {
            if (slot >= NPOST) break;
            int bit = __ffs(m) - 1;
            pos[slot++] = lane * 32 + bit;
            m &= (m - 1);
        }
    }
    __syncthreads();

    {
        int p = pos[t];
        float r0 = 0.f, r1 = 0.f, r2 = 0.f, r3 = 0.f, r4 = 0.f, r5 = 0.f, r6 = 0.f;
        float l0 = 0.f, l1 = 0.f, l2 = 0.f, score = 0.f, lab = 1.f;
        if (p >= 0) {
            int sel = g_topidx[b][p];
            const float* bp = boxes + (size_t)(b * NB + sel) * 7;
            r0 = bp[0]; r1 = bp[1]; r2 = bp[2]; r3 = bp[3]; r4 = bp[4]; r5 = bp[5]; r6 = bp[6];
            const float* cp = cls + (size_t)(b * NB + sel) * 3;
            l0 = cp[0]; l1 = cp[1]; l2 = cp[2];
            int a = 0; float best = l0;
            if (l1 > best) { best = l1; a = 1; }
            if (l2 > best) { best = l2; a = 2; }
            score = best; lab = (float)(a + 1);
        }
        int s = b * NPOST + t;
        float* ro = out + (size_t)s * 7;
        ro[0] = r0; ro[1] = r1; ro[2] = r2; ro[3] = r3; ro[4] = r4; ro[5] = r5; ro[6] = r6;
        out[BATCH * NPOST * 7 + s] = score;
        out[BATCH * NPOST * 8 + s] = lab;
        float* lo = out + BATCH * NPOST * 9 + (size_t)s * 3;
        lo[0] = l0; lo[1] = l1; lo[2] = l2;
    }
}

// ---------------- launch ----------------
extern "C" void kernel_launch(void* const* d_in, const int* in_sizes, int n_in,
                              void* d_out, int out_size) {
    const float* boxes = (const float*)d_in[0];
    const float* cls   = (const float*)d_in[1];
    if (n_in >= 2 && in_sizes[0] == BATCH * NB * 3) {
        const float* tmp = boxes; boxes = cls; cls = tmp;
    }
    float* out = (float*)d_out;
    (void)out_size;

    k_select<<<BATCH, 1024>>>(cls, boxes);
    k_mask  <<<dim3(NPRE / GB_ROWS, BATCH), 1024>>>();
    k_nmsout<<<BATCH, 512>>>(boxes, cls, out);
}

// round 7
// speedup vs baseline: 5.2525x; 1.2711x over previous
#include <cuda_runtime.h>
#include <stdint.h>
#include <math.h>

#define NB    16384
#define NPRE  1024
#define NPOST 512
#define BATCH 2
#define NMS_THRESH 0.8f
#define NBINS 2048
#define QCAP  6144
#define GB_ROWS 64            // mask rows per block in k_mask

// ---------------- device scratch ----------------
__device__ unsigned int g_u[BATCH][NB];          // mapped score keys
__device__ float2       g_cs[BATCH][NB];         // cos/sin per box
__device__ unsigned int g_hist[BATCH][NBINS];    // zero-init; k_top re-zeroes
__device__ int          g_topidx[BATCH][NPRE];
__device__ float        g_bev[BATCH][NPRE][16];
// per box: [0]x [1]y [2]dx [3]dy [4]cos [5]sin [6..9]cx [10..13]cy [14]area [15]radius
__device__ float4       g_prune[BATCH][NPRE];    // x, y, area, radius
__device__ unsigned int g_mask[BATCH][NPRE][32];
__device__ unsigned int g_rowAny[BATCH][32];

// ---------------- helpers ----------------
__device__ __forceinline__ unsigned fmap(float f) {
    unsigned u = __float_as_uint(f);
    return u ^ ((u & 0x80000000u) ? 0xFFFFFFFFu : 0x80000000u);
}

__device__ __forceinline__ unsigned long long ce_shfl(unsigned long long v, int i,
                                                      int stride, int size) {
    unsigned long long p = __shfl_xor_sync(0xffffffffu, v, stride);
    bool descB = ((i & size) == 0);
    bool lower = ((i & stride) == 0);
    bool keepMax = (descB == lower);
    unsigned long long mx = v > p ? v : p, mn = v > p ? p : v;
    return keepMax ? mx : mn;
}

// =====================================================================
// Kernel 0: wide prep — score keys + histogram + double cos/sin for ALL
// boxes.  grid = (128, BATCH), block = 128  (spreads FP64 across all SMs)
// =====================================================================
__global__ void __launch_bounds__(128)
k_prep(const float* __restrict__ cls, const float* __restrict__ boxes) {
    int b = blockIdx.y;
    int i = blockIdx.x * 128 + threadIdx.x;      // 0..16383
    const float* c = cls + (size_t)(b * NB + i) * 3;
    float s = fmaxf(fmaxf(c[0], c[1]), c[2]);
    unsigned u = fmap(s);
    g_u[b][i] = u;
    atomicAdd(&g_hist[b][u >> 21], 1u);
    float ry = boxes[(size_t)(b * NB + i) * 7 + 6];
    g_cs[b][i] = make_float2((float)cos((double)ry), (float)sin((double)ry));
}

// =====================================================================
// Kernel 1: top-1024 select + BEV assembly (no FP64).  grid=BATCH, 1024thr
// =====================================================================
__global__ void __launch_bounds__(1024, 1)
k_top(const float* __restrict__ boxes) {
    int b = blockIdx.x, t = threadIdx.x;
    __shared__ unsigned long long candA[2048];   // 16 KB
    __shared__ unsigned long long candB[2048];   // 16 KB (aliased: cum+hist2 early)
    unsigned* cum   = (unsigned*)candB;          // [0..2048)
    unsigned* hist2 = ((unsigned*)candB) + 2048; // [2048..4096)
    __shared__ int s_b1, s_chi, s_b2, s_usel2, s_cnt;

    candA[t] = (unsigned long long)t;            // pad keys (unique, tiny)
    candA[t + 1024] = (unsigned long long)(t + 1024);
    if (t == 0) { s_usel2 = 0; s_cnt = 0; s_b2 = 0; }
    if (t < 32) g_rowAny[b][t] = 0u;
    // load histogram, then zero it for the next replay (determinism)
    cum[t] = g_hist[b][t]; cum[t + 1024] = g_hist[b][t + 1024];
    g_hist[b][t] = 0u; g_hist[b][t + 1024] = 0u;
    __syncthreads();

    // suffix scan in place: cum[i] = count of keys with bin >= i
    for (int off = 1; off < NBINS; off <<= 1) {
        unsigned v0 = (t + off < NBINS) ? cum[t + off] : 0u;
        unsigned v1 = (t + 1024 + off < NBINS) ? cum[t + 1024 + off] : 0u;
        __syncthreads();
        cum[t] += v0; cum[t + 1024] += v1;
        __syncthreads();
    }
    for (int i = t; i < NBINS; i += 1024) {
        if (cum[i] >= NPRE && (i == NBINS - 1 || cum[i + 1] < NPRE)) {
            s_b1 = i; s_chi = (i == NBINS - 1) ? 0 : (int)cum[i + 1];
        }
    }
    __syncthreads();
    int b1 = s_b1, chi = s_chi;
    int cnt1 = (int)cum[b1] - chi;

    // load this thread's 16 keys from L2 (written by k_prep)
    unsigned myu[16];
#pragma unroll 4
    for (int k = 0; k < 16; k++) myu[k] = g_u[b][t + k * 1024];

    if (chi + cnt1 > 2048) {      // rare: refine boundary bin by next 11 bits
        __syncthreads();
        hist2[t] = 0u; hist2[t + 1024] = 0u;
        if (t == 0) s_usel2 = 1;
        __syncthreads();
#pragma unroll 4
        for (int k = 0; k < 16; k++) {
            unsigned u = myu[k];
            if ((int)(u >> 21) == b1) atomicAdd(&hist2[(u >> 10) & 0x7FF], 1u);
        }
        __syncthreads();
        for (int off = 1; off < NBINS; off <<= 1) {
            unsigned v0 = (t + off < NBINS) ? hist2[t + off] : 0u;
            unsigned v1 = (t + 1024 + off < NBINS) ? hist2[t + 1024 + off] : 0u;
            __syncthreads();
            hist2[t] += v0; hist2[t + 1024] += v1;
            __syncthreads();
        }
        int target2 = NPRE - chi;
        for (int i = t; i < NBINS; i += 1024) {
            if ((int)hist2[i] >= target2 && (i == NBINS - 1 || (int)hist2[i + 1] < target2))
                s_b2 = i;
        }
        __syncthreads();
    }

    // compact candidates into candA
    int usel2 = s_usel2, b2 = s_b2;
#pragma unroll 4
    for (int k = 0; k < 16; k++) {
        unsigned u = myu[k];
        int bin = (int)(u >> 21);
        bool take = (bin > b1) ||
                    (bin == b1 && (!usel2 || (int)((u >> 10) & 0x7FF) >= b2));
        if (take) {
            int p = atomicAdd(&s_cnt, 1);
            if (p < 2048) {
                int e = t + k * 1024;
                candA[p] = ((unsigned long long)u << 32) | (unsigned)(~(unsigned)e);
            }
        }
    }
    __syncthreads();

    // ---- sort phase 1: each warp sorts its 64-key chunk in registers (desc) ----
    {
        int w = t >> 5, l = t & 31;
        unsigned long long v0 = candA[w * 64 + l];
        unsigned long long v1 = candA[w * 64 + 32 + l];
        int i0 = l, i1 = l + 32;
#pragma unroll
        for (int size = 2; size <= 64; size <<= 1) {
#pragma unroll
            for (int stride = size >> 1; stride > 0; stride >>= 1) {
                if (stride == 32) {
                    bool descB = ((i0 & size) == 0);
                    unsigned long long mx = v0 > v1 ? v0 : v1;
                    unsigned long long mn = v0 > v1 ? v1 : v0;
                    v0 = descB ? mx : mn; v1 = descB ? mn : mx;
                } else {
                    v0 = ce_shfl(v0, i0, stride, size);
                    v1 = ce_shfl(v1, i1, stride, size);
                }
            }
        }
        candA[w * 64 + l] = v0;
        candA[w * 64 + 32 + l] = v1;
    }
    __syncthreads();

    // ---- sort phase 2: 5 merge rounds via binary search (32 runs -> 1) ----
    {
        unsigned long long* src = candA;
        unsigned long long* dst = candB;
#pragma unroll
        for (int r = 0; r < 5; r++) {
            int L = 64 << r;
#pragma unroll
            for (int h = 0; h < 2; h++) {
                int p = t + h * 1024;
                unsigned long long key = src[p];
                bool first = ((p & L) == 0);
                int pairBase = p & ~(2 * L - 1);
                int idxInRun = p & (L - 1);
                int otherBase = pairBase + (first ? L : 0);
                int lo = 0, hi = L;
                while (lo < hi) {
                    int mid = (lo + hi) >> 1;
                    if (src[otherBase + mid] > key) lo = mid + 1; else hi = mid;
                }
                dst[pairBase + idxInRun + lo] = key;
            }
            __syncthreads();
            unsigned long long* tmp = src; src = dst; dst = tmp;
        }
    }

    // ---- top-1024: indices + BEV geometry (cos/sin precomputed) ----
    if (t < NPRE) {
        int sel = (int)(~(unsigned)(candB[t] & 0xFFFFFFFFULL));
        g_topidx[b][t] = sel;
        const float* p = boxes + (size_t)(b * NB + sel) * 7;
        float x = p[0], y = p[1], dx = p[3], dy = p[4];
        float2 cs = g_cs[b][sel];
        float c = cs.x, s = cs.y;
        float* o = g_bev[b][t];
        o[0] = x; o[1] = y; o[2] = dx; o[3] = dy; o[4] = c; o[5] = s;
        const float offx[4] = { 0.5f, -0.5f, -0.5f,  0.5f };
        const float offy[4] = { 0.5f,  0.5f, -0.5f, -0.5f };
#pragma unroll
        for (int q = 0; q < 4; q++) {
            float lx = dx * offx[q], ly = dy * offy[q];
            o[6 + q]  = x + lx * c - ly * s;
            o[10 + q] = y + lx * s + ly * c;
        }
        float area = dx * dy;
        float rad  = 0.5f * sqrtf(dx * dx + dy * dy);
        o[14] = area; o[15] = rad;
        g_prune[b][t] = make_float4(x, y, area, rad);
    }
}

// ---------------- faithful pairwise IoU (register-only) ----------------
__device__ float pair_iou(const float* __restrict__ A, const float* __restrict__ B) {
    float ax[4], ay[4], bx[4], by[4];
#pragma unroll
    for (int k = 0; k < 4; k++) { ax[k] = A[6 + k]; ay[k] = A[10 + k]; bx[k] = B[6 + k]; by[k] = B[10 + k]; }
    float dax[4], day[4], dbx[4], dby[4];
#pragma unroll
    for (int k = 0; k < 4; k++) {
        dax[k] = ax[(k + 1) & 3] - ax[k];  day[k] = ay[(k + 1) & 3] - ay[k];
        dbx[k] = bx[(k + 1) & 3] - bx[k];  dby[k] = by[(k + 1) & 3] - by[k];
    }
    float P[32], Q[32], ANG[32];
    bool mk[24];
#pragma unroll
    for (int p = 0; p < 4; p++) {
#pragma unroll
        for (int q = 0; q < 4; q++) {
            int id = p * 4 + q;
            float den = dax[p] * dby[q] - day[p] * dbx[q];
            float ddx = bx[q] - ax[p], ddy = by[q] - ay[p];
            bool nz = fabsf(den) > 1e-8f;
            float dens = nz ? den : 1.0f;
            float tt = (ddx * dby[q] - ddy * dbx[q]) / dens;
            float uu = (ddx * day[p] - ddy * dax[p]) / dens;
            mk[id] = nz && tt >= 0.f && tt <= 1.f && uu >= 0.f && uu <= 1.f;
            P[id] = ax[p] + tt * dax[p];
            Q[id] = ay[p] + tt * day[p];
        }
    }
    float Bx = B[0], By = B[1], Bdx = B[2], Bdy = B[3], Bc = B[4], Bs = B[5];
    float Ax = A[0], Ay = A[1], Adx = A[2], Ady = A[3], Ac = A[4], As = A[5];
#pragma unroll
    for (int k = 0; k < 4; k++) {
        P[16 + k] = ax[k]; Q[16 + k] = ay[k];
        float rx = ax[k] - Bx, ry = ay[k] - By;
        float qx = rx * Bc + ry * Bs, qy = -rx * Bs + ry * Bc;
        mk[16 + k] = (fabsf(qx) <= Bdx * 0.5f + 1e-5f) && (fabsf(qy) <= Bdy * 0.5f + 1e-5f);
        P[20 + k] = bx[k]; Q[20 + k] = by[k];
        float rx2 = bx[k] - Ax, ry2 = by[k] - Ay;
        float qx2 = rx2 * Ac + ry2 * As, qy2 = -rx2 * As + ry2 * Ac;
        mk[20 + k] = (fabsf(qx2) <= Adx * 0.5f + 1e-5f) && (fabsf(qy2) <= Ady * 0.5f + 1e-5f);
    }
    int cnt = 0; float sx = 0.f, sy = 0.f;
#pragma unroll
    for (int k = 0; k < 24; k++) if (mk[k]) { cnt++; sx += P[k]; sy += Q[k]; }
    float inv = 1.0f / (float)(cnt > 0 ? cnt : 1);
    float cx = sx * inv, cy = sy * inv;
#pragma unroll
    for (int k = 0; k < 24; k++)
        ANG[k] = mk[k] ? atan2f(Q[k] - cy, P[k] - cx) : 1e9f;
#pragma unroll
    for (int k = 24; k < 32; k++) { ANG[k] = 1e30f; P[k] = 0.f; Q[k] = 0.f; }
#pragma unroll
    for (int size = 2; size <= 32; size <<= 1) {
#pragma unroll
        for (int stride = size >> 1; stride > 0; stride >>= 1) {
#pragma unroll
            for (int i = 0; i < 32; i++) {
                int j = i ^ stride;
                if (j > i) {
                    bool up = ((i & size) == 0);
                    bool sw = up ? (ANG[i] > ANG[j]) : (ANG[i] < ANG[j]);
                    float t0 = sw ? ANG[j] : ANG[i]; float t1 = sw ? ANG[i] : ANG[j];
                    ANG[i] = t0; ANG[j] = t1;
                    float p0 = sw ? P[j] : P[i];     float p1 = sw ? P[i] : P[j];
                    P[i] = p0; P[j] = p1;
                    float q0 = sw ? Q[j] : Q[i];     float q1 = sw ? Q[i] : Q[j];
                    Q[i] = q0; Q[j] = q1;
                }
            }
        }
    }
    float fx = P[0], fy = Q[0];
    float cr = 0.f;
#pragma unroll
    for (int k = 0; k < 24; k++) {
        int kn = (k + 1) % 24;
        float xk = (k  < cnt) ? P[k]  : fx;
        float yk = (k  < cnt) ? Q[k]  : fy;
        float xn = (kn < cnt) ? P[kn] : fx;
        float yn = (kn < cnt) ? Q[kn] : fy;
        cr += xk * yn - yk * xn;
    }
    float inter = 0.5f * fabsf(cr);
    return inter / fmaxf(A[14] + B[14] - inter, 1e-6f);
}

// =====================================================================
// Kernel 2: fused prune + exact IoU -> suppression bitmask + rowAny.
// grid = (NPRE/GB_ROWS, BATCH), block = 256  (full register budget, no spills)
// =====================================================================
__global__ void __launch_bounds__(256, 1) k_mask() {
    int b = blockIdx.y, blk = blockIdx.x, t = threadIdx.x;
    int i0 = blk * GB_ROWS;
    __shared__ float4 spr[NPRE];           // 16 KB
    __shared__ unsigned q[QCAP];           // 24 KB
    __shared__ int qc;
    if (t == 0) qc = 0;
    for (int k = t; k < NPRE; k += 256) spr[k] = g_prune[b][k];
    // zero this block's strip of the mask (sole writer of these rows)
    for (int k = t; k < GB_ROWS * 32; k += 256)
        ((unsigned*)g_mask[b][i0])[k] = 0u;
    __syncthreads();

    float4 pj[4];
#pragma unroll
    for (int jj = 0; jj < 4; jj++) pj[jj] = spr[t + jj * 256];

    for (int r = 0; r < GB_ROWS; r++) {
        int i = i0 + r;
        float4 pi = spr[i];
#pragma unroll
        for (int jj = 0; jj < 4; jj++) {
            int j = t + jj * 256;
            if (j > i) {
                float ddx = pi.x - pj[jj].x, ddy = pi.y - pj[jj].y;
                float rs = pi.w + pj[jj].w + 1e-3f;
                if (ddx * ddx + ddy * ddy < rs * rs) {
                    float amin = fminf(pi.z, pj[jj].z), amax = fmaxf(pi.z, pj[jj].z);
                    if (amin > 0.79f * amax) {
                        int p = atomicAdd(&qc, 1);
                        if (p < QCAP) q[p] = ((unsigned)i << 16) | (unsigned)j;
                        else {  // overflow fallback (never expected)
                            float iou = pair_iou(g_bev[b][i], g_bev[b][j]);
                            if (iou > NMS_THRESH)
                                atomicOr(&g_mask[b][i][j >> 5], 1u << (j & 31));
                        }
                    }
                }
            }
        }
    }
    __syncthreads();
    int n = min(qc, QCAP);
    for (int p = t; p < n; p += 256) {
        unsigned pr = q[p];
        int i = (int)(pr >> 16), jj = (int)(pr & 0xFFFFu);
        float iou = pair_iou(g_bev[b][i], g_bev[b][jj]);
        if (iou > NMS_THRESH) atomicOr(&g_mask[b][i][jj >> 5], 1u << (jj & 31));
    }
    __syncthreads();
    // rowAny for this strip: 8 warps x 8 sweeps covers 64 rows
    {
        int lane = t & 31, w = t >> 5;
#pragma unroll
        for (int sweep = 0; sweep < 8; sweep++) {
            int row = i0 + sweep * 8 + w;
            unsigned val = g_mask[b][row][lane];
            bool any = __any_sync(0xffffffffu, val != 0u);
            if (lane == 0 && any)
                atomicOr(&g_rowAny[b][row >> 5], 1u << (row & 31));
        }
    }
}

// =====================================================================
// Kernel 3: greedy NMS with sparsity skips + output write.  grid=BATCH
// out layout: rois[2][512][7] | scores[2][512] | labels[2][512] | logits[2][512][3]
// =====================================================================
__global__ void __launch_bounds__(512, 1)
k_nmsout(const float* __restrict__ boxes, const float* __restrict__ cls,
         float* __restrict__ out) {
    int b = blockIdx.x, t = threadIdx.x;
    __shared__ unsigned s_rowAny[32];
    __shared__ int pos[NPOST];
    if (t < 32) s_rowAny[t] = g_rowAny[b][t];
    pos[t] = -1;
    __syncthreads();

    if (t < 32) {
        int lane = t;
        unsigned supp = 0u;
        const unsigned* __restrict__ M = &g_mask[b][0][0];
        for (int c = 0; c < 32; c++) {
            unsigned ra = s_rowAny[c];
            unsigned cur = __shfl_sync(0xffffffffu, supp, c);
            if (ra & ~cur) {
                unsigned d[32];
#pragma unroll
                for (int k = 0; k < 32; k++)
                    d[k] = ((ra >> k) & 1u) ? __ldg(&M[(c * 32 + k) * 32 + c]) : 0u;
#pragma unroll
                for (int k = 0; k < 32; k++)
                    cur |= ((cur >> k) & 1u) ? 0u : d[k];
                unsigned act = ~cur & ra;
                while (act) {
                    int k = __ffs(act) - 1;
                    supp |= __ldg(&M[(c * 32 + k) * 32 + lane]);
                    act &= act - 1;
                }
            }
        }
        unsigned keep = ~supp;
        int cc = __popc(keep);
        int incl = cc;
        for (int o = 1; o < 32; o <<= 1) {
            int v = __shfl_up_sync(0xffffffffu, incl, o);
            if (lane >= o) incl += v;
        }
        int excl = incl - cc;
        __syncwarp();
        unsigned m = keep;
        int slot = excl;
        while (m) {
            if (slot >= NPOST) break;
            int bit = __ffs(m) - 1;
            pos[slot++] = lane * 32 + bit;
            m &= (m - 1);
        }
    }
    __syncthreads();

    {
        int p = pos[t];
        float r0 = 0.f, r1 = 0.f, r2 = 0.f, r3 = 0.f, r4 = 0.f, r5 = 0.f, r6 = 0.f;
        float l0 = 0.f, l1 = 0.f, l2 = 0.f, score = 0.f, lab = 1.f;
        if (p >= 0) {
            int sel = g_topidx[b][p];
            const float* bp = boxes + (size_t)(b * NB + sel) * 7;
            r0 = bp[0]; r1 = bp[1]; r2 = bp[2]; r3 = bp[3]; r4 = bp[4]; r5 = bp[5]; r6 = bp[6];
            const float* cp = cls + (size_t)(b * NB + sel) * 3;
            l0 = cp[0]; l1 = cp[1]; l2 = cp[2];
            int a = 0; float best = l0;
            if (l1 > best) { best = l1; a = 1; }
            if (l2 > best) { best = l2; a = 2; }
            score = best; lab = (float)(a + 1);
        }
        int s = b * NPOST + t;
        float* ro = out + (size_t)s * 7;
        ro[0] = r0; ro[1] = r1; ro[2] = r2; ro[3] = r3; ro[4] = r4; ro[5] = r5; ro[6] = r6;
        out[BATCH * NPOST * 7 + s] = score;
        out[BATCH * NPOST * 8 + s] = lab;
        float* lo = out + BATCH * NPOST * 9 + (size_t)s * 3;
        lo[0] = l0; lo[1] = l1; lo[2] = l2;
    }
}

// ---------------- launch ----------------
extern "C" void kernel_launch(void* const* d_in, const int* in_sizes, int n_in,
                              void* d_out, int out_size) {
    const float* boxes = (const float*)d_in[0];
    const float* cls   = (const float*)d_in[1];
    if (n_in >= 2 && in_sizes[0] == BATCH * NB * 3) {
        const float* tmp = boxes; boxes = cls; cls = tmp;
    }
    float* out = (float*)d_out;
    (void)out_size;

    k_prep  <<<dim3(128, BATCH), 128>>>(cls, boxes);
    k_top   <<<BATCH, 1024>>>(boxes);
    k_mask  <<<dim3(NPRE / GB_ROWS, BATCH), 256>>>();
    k_nmsout<<<BATCH, 512>>>(boxes, cls, out);
}